// round 13
// baseline (speedup 1.0000x reference)
#include <cuda_runtime.h>
#include <cuda_bf16.h>
#include <math_constants.h>

// ShiftNMF: out[n,m] = Re( sum_d softplus(W[n,d]) * exp(-2*pi*i*tau[n,d]*m/M) * Hft[d,m] )
// Hft = full FFT of softplus(H). Output float32 = Re(V), out_size = N*M.

#define N_ROWS 1024
#define RANK   16
#define M_LEN  4096
#define LOG2M  12

__device__ float2 g_Hft[RANK * M_LEN];

__device__ __forceinline__ float softplus_accurate(float x) {
    return (x > 20.0f) ? x : log1pf(expf(x));
}
__device__ __forceinline__ float2 cmul(float2 a, float2 b) {
    return make_float2(a.x * b.x - a.y * b.y, a.x * b.y + a.y * b.x);
}

// Packed f32x2 helpers (Blackwell FFMA2 — only reachable via PTX).
__device__ __forceinline__ unsigned long long pack2(float lo, float hi) {
    unsigned long long r;
    asm("mov.b64 %0, {%1, %2};" : "=l"(r) : "f"(lo), "f"(hi));
    return r;
}
__device__ __forceinline__ void unpack2(unsigned long long v, float& lo, float& hi) {
    asm("mov.b64 {%0, %1}, %2;" : "=f"(lo), "=f"(hi) : "l"(v));
}
#define FMA2(dst, a, b, c) \
    asm("fma.rn.f32x2 %0, %1, %2, %3;" : "=l"(dst) : "l"(a), "l"(b), "l"(c))

// ---------------------------------------------------------------------------
// Kernel 1: 16 x 4096-pt FFT of softplus(H), radix-4 DIT (validated).
// ---------------------------------------------------------------------------
#define FFT_THREADS 1024

__global__ void __launch_bounds__(FFT_THREADS) fft_hft_kernel(const float* __restrict__ H) {
    __shared__ float2 buf[M_LEN];
    __shared__ float2 tw[M_LEN / 2];
    const int row = blockIdx.x;
    const int tid = threadIdx.x;

    for (int j = tid; j < M_LEN / 2; j += FFT_THREADS) {
        float s, c;
        sincospif(-2.0f * (float)j / (float)M_LEN, &s, &c);
        tw[j] = make_float2(c, s);
    }
    for (int i = tid; i < M_LEN; i += FFT_THREADS) {
        unsigned r = __brev((unsigned)i) >> (32 - LOG2M);
        r = ((r & 0x555u) << 1) | ((r >> 1) & 0x555u);
        float v = softplus_accurate(H[row * M_LEN + i]);
        buf[r] = make_float2(v, 0.0f);
    }
    __syncthreads();

    #pragma unroll 1
    for (int s = 1; s <= 6; s++) {
        const int q   = 1 << (2 * (s - 1));
        const int tsh = LOG2M - 2 * s;
        const int k   = tid & (q - 1);
        const int g   = tid >> (2 * (s - 1));
        const int base = g * (q << 2) + k;

        float2 y0 = buf[base];
        float2 y1 = buf[base + q];
        float2 y2 = buf[base + 2 * q];
        float2 y3 = buf[base + 3 * q];

        float2 w1 = tw[k << tsh];
        float2 w2 = tw[(2 * k) << tsh];
        float2 w3 = cmul(w1, w2);

        float2 t1 = cmul(w1, y1);
        float2 t2 = cmul(w2, y2);
        float2 t3 = cmul(w3, y3);

        float2 u0 = make_float2(y0.x + t2.x, y0.y + t2.y);
        float2 u1 = make_float2(y0.x - t2.x, y0.y - t2.y);
        float2 u2 = make_float2(t1.x + t3.x, t1.y + t3.y);
        float2 u3 = make_float2(t1.x - t3.x, t1.y - t3.y);

        buf[base]         = make_float2(u0.x + u2.x, u0.y + u2.y);
        buf[base + 2 * q] = make_float2(u0.x - u2.x, u0.y - u2.y);
        buf[base + q]     = make_float2(u1.x + u3.y, u1.y - u3.x);
        buf[base + 3 * q] = make_float2(u1.x - u3.y, u1.y + u3.x);
        __syncthreads();
    }

    for (int i = tid; i < M_LEN; i += FFT_THREADS) {
        g_Hft[row * M_LEN + i] = buf[i];
    }
}

// ---------------------------------------------------------------------------
// Kernel 2: 4-rows-per-warp variant (LDS bytes per FFMA halved vs R12).
// CTA = 128 thr = 4 warps; warp owns 4 n-rows; CTA tile = 16 rows x 256 m.
// 16 d-passes of 1 rank, double-buffered (2 KB tiles) w/ register prefetch.
// Each LDS.64 of h feeds 4 rows -> smem traffic 268 MB (~7.5us floor),
// level with the 4.19M warp-FFMA2 floor (~7.5us).
// ---------------------------------------------------------------------------
#define THREADS 128
#define CHUNK_M 256
#define M_ITERS (CHUNK_M / 32)            // 8
#define NPASSES RANK                      // 16, one d per pass
#define ROWS_W  4
#define WARPS_PER_CTA 4
#define ROWS_CTA (WARPS_PER_CTA * ROWS_W) // 16
#define TWO_PI 6.28318530717958647692f

__global__ void __launch_bounds__(THREADS, 4) shiftnmf_main_kernel(
    const float* __restrict__ W,
    const float* __restrict__ tau,
    float* __restrict__ out,
    unsigned long long max_elems)
{
    __shared__ float2 sh[2][CHUNK_M];            // 4 KB ping-pong (1 rank/pass)
    __shared__ float4 tb[ROWS_CTA * RANK];       // 4 KB: (sw, p, cs, ss)

    const int tid    = threadIdx.x;
    const int lane   = tid & 31;
    const int warp   = tid >> 5;
    const int m_base = blockIdx.x * CHUNK_M;
    const int nblk   = blockIdx.y * ROWS_CTA;

    // Seed table: 256 entries (16 rows x 16 d), two per thread.
    #pragma unroll
    for (int q = 0; q < 2; q++) {
        const int idx = q * THREADS + tid;
        const int rl  = idx >> 4;
        const int d   = idx & 15;
        const int n   = nblk + rl;
        float t  = tau[n * RANK + d];
        float sw = softplus_accurate(W[n * RANK + d]);
        float ss, cs;
        sincospif(-t * (64.0f / (float)M_LEN), &ss, &cs);   // 32-step angle
        tb[rl * RANK + d] = make_float4(sw, -TWO_PI * t / (float)M_LEN, cs, ss);
    }

    const int ld_e = tid;   // float4 index in the 256-complex tile (128 total)

    // Load pass 0 tile (d=0) into buffer 0: 1 float4 per thread.
    {
        float4 v = *reinterpret_cast<const float4*>(
            &g_Hft[0 * M_LEN + m_base + ld_e * 2]);
        *reinterpret_cast<float4*>(&sh[0][ld_e * 2]) = v;
    }
    __syncthreads();   // tile 0 + seed table visible

    unsigned long long acc2[ROWS_W][M_ITERS];
    #pragma unroll
    for (int r = 0; r < ROWS_W; r++)
        #pragma unroll
        for (int i = 0; i < M_ITERS; i++) acc2[r][i] = 0ULL;

    const float fm0 = (float)(m_base + lane);

    #pragma unroll 1
    for (int pass = 0; pass < NPASSES; pass++) {
        const float2* __restrict__ cur = sh[pass & 1];

        // Register prefetch of next pass's tile (hides L2 latency).
        float4 p0;
        const bool pf = (pass < NPASSES - 1);
        if (pf) {
            p0 = *reinterpret_cast<const float4*>(
                &g_Hft[(pass + 1) * M_LEN + m_base + ld_e * 2]);
        }

        // Seed packed rotators (4 rows, 1 rank) from the smem table.
        unsigned long long A2[ROWS_W], B2[ROWS_W], KP2[ROWS_W], KN2[ROWS_W];
        #pragma unroll
        for (int r = 0; r < ROWS_W; r++) {
            float4 e = tb[(warp * ROWS_W + r) * RANK + pass];
            float s0, c0;
            __sincosf(e.y * fm0, &s0, &c0);
            float cr = e.x * c0;
            float ci = e.x * s0;
            float k  = e.z + e.z;
            A2[r]  = pack2(cr, ci);
            B2[r]  = pack2(-fmaf(cr, e.z,  ci * e.w),
                            fmaf(cr, e.w, -ci * e.z));
            KP2[r] = pack2(k, k);
            KN2[r] = pack2(-k, -k);
        }

        #pragma unroll
        for (int it = 0; it < M_ITERS; it++) {
            const int ml = it * 32 + lane;
            unsigned long long h2 =
                *reinterpret_cast<const unsigned long long*>(&cur[ml]);
            #pragma unroll
            for (int r = 0; r < ROWS_W; r++) {
                if ((it & 1) == 0) {
                    FMA2(acc2[r][it], A2[r], h2, acc2[r][it]);
                    FMA2(B2[r], KP2[r], A2[r], B2[r]);
                } else {
                    FMA2(acc2[r][it], B2[r], h2, acc2[r][it]);
                    FMA2(A2[r], KN2[r], B2[r], A2[r]);
                }
            }
        }

        // Stage prefetched tile; single barrier per pass.
        if (pf) {
            float2* nxt = sh[(pass + 1) & 1];
            *reinterpret_cast<float4*>(&nxt[ld_e * 2]) = p0;
            __syncthreads();
        }
    }

    #pragma unroll
    for (int r = 0; r < ROWS_W; r++) {
        const unsigned long long row_base =
            (unsigned long long)(nblk + warp * ROWS_W + r) * M_LEN + m_base;
        #pragma unroll
        for (int it = 0; it < M_ITERS; it++) {
            float ax, ay;
            unpack2(acc2[r][it], ax, ay);
            float val = ((it & 2) == 0) ? (ax - ay) : (ay - ax);
            unsigned long long fi = row_base + (unsigned long long)(it * 32 + lane);
            if (fi < max_elems) out[fi] = val;
        }
    }
}

// ---------------------------------------------------------------------------
extern "C" void kernel_launch(void* const* d_in, const int* in_sizes, int n_in,
                              void* d_out, int out_size) {
    // H = strictly largest input; remaining two in given order = W, tau_tilde.
    int hi = 0;
    for (int i = 1; i < n_in; i++)
        if (in_sizes[i] > in_sizes[hi]) hi = i;

    const float* H = (const float*)d_in[hi];
    const float* wt[2] = {nullptr, nullptr};
    int nwt = 0;
    for (int i = 0; i < n_in && nwt < 2; i++)
        if (i != hi) wt[nwt++] = (const float*)d_in[i];
    const float* W   = wt[0];
    const float* tau = (wt[1] != nullptr) ? wt[1] : wt[0];

    float* out = (float*)d_out;

    unsigned long long max_elems = (unsigned long long)out_size;
    const unsigned long long full = (unsigned long long)N_ROWS * M_LEN;
    if (max_elems > full) max_elems = full;

    fft_hft_kernel<<<RANK, FFT_THREADS>>>(H);

    dim3 grid(M_LEN / CHUNK_M, N_ROWS / ROWS_CTA);  // (16, 64) = 1024 CTAs
    shiftnmf_main_kernel<<<grid, THREADS>>>(W, tau, out, max_elems);
}

// round 14
// speedup vs baseline: 1.0654x; 1.0654x over previous
#include <cuda_runtime.h>
#include <cuda_bf16.h>
#include <math_constants.h>

// ShiftNMF: out[n,m] = Re( sum_d softplus(W[n,d]) * exp(-2*pi*i*tau[n,d]*m/M) * Hft[d,m] )
// Hft = full FFT of softplus(H). Output float32 = Re(V), out_size = N*M.

#define N_ROWS 1024
#define RANK   16
#define M_LEN  4096
#define LOG2M  12

__device__ float2 g_Hft[RANK * M_LEN];

__device__ __forceinline__ float softplus_accurate(float x) {
    return (x > 20.0f) ? x : log1pf(expf(x));
}
__device__ __forceinline__ float2 cmul(float2 a, float2 b) {
    return make_float2(a.x * b.x - a.y * b.y, a.x * b.y + a.y * b.x);
}

// Packed f32x2 helpers (Blackwell FFMA2 — only reachable via PTX).
__device__ __forceinline__ unsigned long long pack2(float lo, float hi) {
    unsigned long long r;
    asm("mov.b64 %0, {%1, %2};" : "=l"(r) : "f"(lo), "f"(hi));
    return r;
}
__device__ __forceinline__ void unpack2(unsigned long long v, float& lo, float& hi) {
    asm("mov.b64 {%0, %1}, %2;" : "=f"(lo), "=f"(hi) : "l"(v));
}
#define FMA2(dst, a, b, c) \
    asm("fma.rn.f32x2 %0, %1, %2, %3;" : "=l"(dst) : "l"(a), "l"(b), "l"(c))

// ---------------------------------------------------------------------------
// Kernel 1: 16 x 4096-pt FFT of softplus(H), radix-4 DIT (validated).
// ---------------------------------------------------------------------------
#define FFT_THREADS 1024

__global__ void __launch_bounds__(FFT_THREADS) fft_hft_kernel(const float* __restrict__ H) {
    __shared__ float2 buf[M_LEN];
    __shared__ float2 tw[M_LEN / 2];
    const int row = blockIdx.x;
    const int tid = threadIdx.x;

    for (int j = tid; j < M_LEN / 2; j += FFT_THREADS) {
        float s, c;
        sincospif(-2.0f * (float)j / (float)M_LEN, &s, &c);
        tw[j] = make_float2(c, s);
    }
    for (int i = tid; i < M_LEN; i += FFT_THREADS) {
        unsigned r = __brev((unsigned)i) >> (32 - LOG2M);
        r = ((r & 0x555u) << 1) | ((r >> 1) & 0x555u);
        float v = softplus_accurate(H[row * M_LEN + i]);
        buf[r] = make_float2(v, 0.0f);
    }
    __syncthreads();

    #pragma unroll 1
    for (int s = 1; s <= 6; s++) {
        const int q   = 1 << (2 * (s - 1));
        const int tsh = LOG2M - 2 * s;
        const int k   = tid & (q - 1);
        const int g   = tid >> (2 * (s - 1));
        const int base = g * (q << 2) + k;

        float2 y0 = buf[base];
        float2 y1 = buf[base + q];
        float2 y2 = buf[base + 2 * q];
        float2 y3 = buf[base + 3 * q];

        float2 w1 = tw[k << tsh];
        float2 w2 = tw[(2 * k) << tsh];
        float2 w3 = cmul(w1, w2);

        float2 t1 = cmul(w1, y1);
        float2 t2 = cmul(w2, y2);
        float2 t3 = cmul(w3, y3);

        float2 u0 = make_float2(y0.x + t2.x, y0.y + t2.y);
        float2 u1 = make_float2(y0.x - t2.x, y0.y - t2.y);
        float2 u2 = make_float2(t1.x + t3.x, t1.y + t3.y);
        float2 u3 = make_float2(t1.x - t3.x, t1.y - t3.y);

        buf[base]         = make_float2(u0.x + u2.x, u0.y + u2.y);
        buf[base + 2 * q] = make_float2(u0.x - u2.x, u0.y - u2.y);
        buf[base + q]     = make_float2(u1.x + u3.y, u1.y - u3.x);
        buf[base + 3 * q] = make_float2(u1.x - u3.y, u1.y + u3.x);
        __syncthreads();
    }

    for (int i = tid; i < M_LEN; i += FFT_THREADS) {
        g_Hft[row * M_LEN + i] = buf[i];
    }
}

// ---------------------------------------------------------------------------
// Kernel 2: LDG-direct, zero-barrier mainloop.
// CTA = 128 thr = 4 warps; warp owns 2 n-rows; CTA tile = 8 rows x 256 m.
// d outer (seed 2 rotators from smem table), it inner (1 LDG.64 hitting
// L1 after first warp + 4 FMA2). No smem Hft tile, no ping-pong, no
// barriers after the seed table -> low regs, high occupancy, 4-pipe overlap.
// ---------------------------------------------------------------------------
#define THREADS 128
#define CHUNK_M 256
#define M_ITERS (CHUNK_M / 32)            // 8
#define ROWS_W  2
#define WARPS_PER_CTA 4
#define ROWS_CTA (WARPS_PER_CTA * ROWS_W) // 8
#define TWO_PI 6.28318530717958647692f

__global__ void __launch_bounds__(THREADS, 6) shiftnmf_main_kernel(
    const float* __restrict__ W,
    const float* __restrict__ tau,
    float* __restrict__ out,
    unsigned long long max_elems)
{
    __shared__ float4 tb[ROWS_CTA * RANK];       // 2 KB: (sw, p, cs, ss)

    const int tid    = threadIdx.x;
    const int lane   = tid & 31;
    const int warp   = tid >> 5;
    const int m_base = blockIdx.x * CHUNK_M;
    const int nblk   = blockIdx.y * ROWS_CTA;

    // Seed table: 128 entries (8 rows x 16 d), one thread each.
    {
        const int rl = tid >> 4;
        const int d  = tid & 15;
        const int n  = nblk + rl;
        float t  = tau[n * RANK + d];
        float sw = softplus_accurate(W[n * RANK + d]);
        float ss, cs;
        sincospif(-t * (64.0f / (float)M_LEN), &ss, &cs);   // 32-step angle
        tb[rl * RANK + d] = make_float4(sw, -TWO_PI * t / (float)M_LEN, cs, ss);
    }
    __syncthreads();   // only barrier in the kernel

    unsigned long long acc2[ROWS_W][M_ITERS];
    #pragma unroll
    for (int r = 0; r < ROWS_W; r++)
        #pragma unroll
        for (int i = 0; i < M_ITERS; i++) acc2[r][i] = 0ULL;

    const float fm0 = (float)(m_base + lane);
    // Per-thread base pointer into Hft for this m-chunk; loads at
    // [hp + d*M_LEN + it*32] resolve to immediate-offset LDG.64.
    const float2* __restrict__ hp = g_Hft + m_base + lane;

    #pragma unroll 1
    for (int d = 0; d < RANK; d++) {
        // Seed packed rotators (2 rows, this d) from the smem table.
        unsigned long long A2[ROWS_W], B2[ROWS_W], KP2[ROWS_W], KN2[ROWS_W];
        #pragma unroll
        for (int r = 0; r < ROWS_W; r++) {
            float4 e = tb[(warp * ROWS_W + r) * RANK + d];
            float s0, c0;
            __sincosf(e.y * fm0, &s0, &c0);
            float cr = e.x * c0;
            float ci = e.x * s0;
            float k  = e.z + e.z;
            A2[r]  = pack2(cr, ci);
            B2[r]  = pack2(-fmaf(cr, e.z,  ci * e.w),
                            fmaf(cr, e.w, -ci * e.z));
            KP2[r] = pack2(k, k);
            KN2[r] = pack2(-k, -k);
        }

        const float2* __restrict__ hd = hp + d * M_LEN;

        #pragma unroll
        for (int it = 0; it < M_ITERS; it++) {
            unsigned long long h2 =
                *reinterpret_cast<const unsigned long long*>(&hd[it * 32]);
            #pragma unroll
            for (int r = 0; r < ROWS_W; r++) {
                if ((it & 1) == 0) {
                    FMA2(acc2[r][it], A2[r], h2, acc2[r][it]);
                    FMA2(B2[r], KP2[r], A2[r], B2[r]);
                } else {
                    FMA2(acc2[r][it], B2[r], h2, acc2[r][it]);
                    FMA2(A2[r], KN2[r], B2[r], A2[r]);
                }
            }
        }
    }

    #pragma unroll
    for (int r = 0; r < ROWS_W; r++) {
        const unsigned long long row_base =
            (unsigned long long)(nblk + warp * ROWS_W + r) * M_LEN + m_base;
        #pragma unroll
        for (int it = 0; it < M_ITERS; it++) {
            float ax, ay;
            unpack2(acc2[r][it], ax, ay);
            float val = ((it & 2) == 0) ? (ax - ay) : (ay - ax);
            unsigned long long fi = row_base + (unsigned long long)(it * 32 + lane);
            if (fi < max_elems) out[fi] = val;
        }
    }
}

// ---------------------------------------------------------------------------
extern "C" void kernel_launch(void* const* d_in, const int* in_sizes, int n_in,
                              void* d_out, int out_size) {
    // H = strictly largest input; remaining two in given order = W, tau_tilde.
    int hi = 0;
    for (int i = 1; i < n_in; i++)
        if (in_sizes[i] > in_sizes[hi]) hi = i;

    const float* H = (const float*)d_in[hi];
    const float* wt[2] = {nullptr, nullptr};
    int nwt = 0;
    for (int i = 0; i < n_in && nwt < 2; i++)
        if (i != hi) wt[nwt++] = (const float*)d_in[i];
    const float* W   = wt[0];
    const float* tau = (wt[1] != nullptr) ? wt[1] : wt[0];

    float* out = (float*)d_out;

    unsigned long long max_elems = (unsigned long long)out_size;
    const unsigned long long full = (unsigned long long)N_ROWS * M_LEN;
    if (max_elems > full) max_elems = full;

    fft_hft_kernel<<<RANK, FFT_THREADS>>>(H);

    dim3 grid(M_LEN / CHUNK_M, N_ROWS / ROWS_CTA);  // (16, 128) = 2048 CTAs
    shiftnmf_main_kernel<<<grid, THREADS>>>(W, tau, out, max_elems);
}